// round 2
// baseline (speedup 1.0000x reference)
#include <cuda_runtime.h>

#define NN 100000
#define D  512

// Scratch (allocation-free rule: __device__ globals)
__device__ __align__(128) float g_buf1[(size_t)NN * D];
__device__ __align__(128) float g_buf2[(size_t)NN * D];
__device__ float g_rsd[NN];

// ---------- packed f32x2 helpers (Blackwell FFMA2 path) ----------
static __device__ __forceinline__ unsigned long long pk2(float x, float y) {
    unsigned long long r;
    asm("mov.b64 %0, {%1, %2};" : "=l"(r) : "f"(x), "f"(y));
    return r;
}
static __device__ __forceinline__ void upk2(unsigned long long v, float& x, float& y) {
    asm("mov.b64 {%0, %1}, %2;" : "=f"(x), "=f"(y) : "l"(v));
}
static __device__ __forceinline__ void fma2(unsigned long long& d,
                                            unsigned long long a,
                                            unsigned long long b) {
    asm("fma.rn.f32x2 %0, %1, %2, %0;" : "+l"(d) : "l"(a), "l"(b));
}

// ---------- degree / inverse-sqrt kernel ----------
__global__ void deg_kernel(const int* __restrict__ ei) {
    int i = blockIdx.x * blockDim.x + threadIdx.x;
    if (i >= NN) return;
    int c = 1;
#pragma unroll
    for (int j = 0; j < 3; j++) c += (ei[i * 3 + j] >= 0);
    g_rsd[i] = rsqrtf((float)c);
}

// ---------- GEMM: C[m,n] = (sum_k A[m,k]*W[n,k] + bias[n]) * rsd[m] ----------
// Tiles: BM=128, BN=128, BK=8. 256 threads, each computes 8x8 via f32x2 pairs.
__global__ __launch_bounds__(256, 2)
void gemm_kernel(const float* __restrict__ A, const float* __restrict__ W,
                 const float* __restrict__ bias, float* __restrict__ C) {
    constexpr int BM = 128, BN = 128, BK = 8;
    __shared__ float As[BK][BM];
    __shared__ float Bs[BK][BN];

    const int m0 = blockIdx.y * BM;
    const int n0 = blockIdx.x * BN;
    const int tid = threadIdx.x;
    const int tx = tid & 15;       // 0..15 -> 8 output cols each
    const int ty = tid >> 4;       // 0..15 -> 8 output rows each
    const int lr = tid >> 1;       // load row within tile: 0..127
    const int lc = (tid & 1) * 4;  // load col: 0 or 4

    const int  arow   = m0 + lr;
    const bool avalid = arow < NN;
    const float* aptr = A + (size_t)arow * D + lc;
    const float* wptr = W + (size_t)(n0 + lr) * D + lc;

    float bs[8];
#pragma unroll
    for (int j = 0; j < 8; j++) bs[j] = bias[n0 + tx * 8 + j];

    unsigned long long acc[8][4];
#pragma unroll
    for (int i = 0; i < 8; i++)
#pragma unroll
        for (int j = 0; j < 4; j++) acc[i][j] = 0ull;  // bits of (0.f, 0.f)

    for (int k0 = 0; k0 < D; k0 += BK) {
        float4 av = make_float4(0.f, 0.f, 0.f, 0.f);
        if (avalid) av = *(const float4*)(aptr + k0);
        float4 wv = *(const float4*)(wptr + k0);

        __syncthreads();
        As[lc + 0][lr] = av.x; As[lc + 1][lr] = av.y;
        As[lc + 2][lr] = av.z; As[lc + 3][lr] = av.w;
        Bs[lc + 0][lr] = wv.x; Bs[lc + 1][lr] = wv.y;
        Bs[lc + 2][lr] = wv.z; Bs[lc + 3][lr] = wv.w;
        __syncthreads();

#pragma unroll
        for (int k = 0; k < BK; k++) {
            float4 a0 = *(const float4*)&As[k][ty * 8];
            float4 a1 = *(const float4*)&As[k][ty * 8 + 4];
            float4 b0 = *(const float4*)&Bs[k][tx * 8];
            float4 b1 = *(const float4*)&Bs[k][tx * 8 + 4];
            unsigned long long bp[4] = {pk2(b0.x, b0.y), pk2(b0.z, b0.w),
                                        pk2(b1.x, b1.y), pk2(b1.z, b1.w)};
            float aa[8] = {a0.x, a0.y, a0.z, a0.w, a1.x, a1.y, a1.z, a1.w};
#pragma unroll
            for (int i = 0; i < 8; i++) {
                unsigned long long ap = pk2(aa[i], aa[i]);
#pragma unroll
                for (int j = 0; j < 4; j++) fma2(acc[i][j], ap, bp[j]);
            }
        }
    }

#pragma unroll
    for (int i = 0; i < 8; i++) {
        int row = m0 + ty * 8 + i;
        if (row >= NN) break;  // rows are consecutive; safe to stop
        float rs = g_rsd[row];
        float o[8];
#pragma unroll
        for (int j = 0; j < 4; j++) upk2(acc[i][j], o[2 * j], o[2 * j + 1]);
        float4 v0, v1;
        v0.x = (o[0] + bs[0]) * rs; v0.y = (o[1] + bs[1]) * rs;
        v0.z = (o[2] + bs[2]) * rs; v0.w = (o[3] + bs[3]) * rs;
        v1.x = (o[4] + bs[4]) * rs; v1.y = (o[5] + bs[5]) * rs;
        v1.z = (o[6] + bs[6]) * rs; v1.w = (o[7] + bs[7]) * rs;
        float* cp = C + (size_t)row * D + n0 + tx * 8;
        *(float4*)cp       = v0;
        *(float4*)(cp + 4) = v1;
    }
}

// ---------- aggregation: out[i] = elu((h[i] + sum_valid h[e]) * rsd[i]) ----------
__global__ void agg_kernel(const float* __restrict__ h,
                           const int* __restrict__ ei,
                           float* __restrict__ out) {
    const size_t node = blockIdx.x;
    const int t = threadIdx.x;  // 0..127, float4 lane
    const float4* hv = (const float4*)h;

    float4 acc = hv[node * 128 + t];
    int e0 = ei[node * 3 + 0];
    int e1 = ei[node * 3 + 1];
    int e2 = ei[node * 3 + 2];
    if (e0 >= 0) { float4 v = hv[(size_t)e0 * 128 + t]; acc.x += v.x; acc.y += v.y; acc.z += v.z; acc.w += v.w; }
    if (e1 >= 0) { float4 v = hv[(size_t)e1 * 128 + t]; acc.x += v.x; acc.y += v.y; acc.z += v.z; acc.w += v.w; }
    if (e2 >= 0) { float4 v = hv[(size_t)e2 * 128 + t]; acc.x += v.x; acc.y += v.y; acc.z += v.z; acc.w += v.w; }

    const float rs = g_rsd[node];
    acc.x *= rs; acc.y *= rs; acc.z *= rs; acc.w *= rs;

    // ELU (alpha=1), matching jax.nn.elu = where(x>0, x, expm1(x))
    acc.x = acc.x > 0.f ? acc.x : expm1f(acc.x);
    acc.y = acc.y > 0.f ? acc.y : expm1f(acc.y);
    acc.z = acc.z > 0.f ? acc.z : expm1f(acc.z);
    acc.w = acc.w > 0.f ? acc.w : expm1f(acc.w);

    ((float4*)out)[node * 128 + t] = acc;
}

extern "C" void kernel_launch(void* const* d_in, const int* in_sizes, int n_in,
                              void* d_out, int out_size) {
    // Robust input binding by element counts (immune to metadata reordering):
    //   x: NN*D = 51,200,000   edge_index: NN*3 = 300,000 (int32!)
    //   W1/W2: 262,144 (in order)   b1/b2: 512 (in order)
    const float* x  = nullptr;
    const int*   ei = nullptr;
    const float* W[2] = {nullptr, nullptr};
    const float* b[2] = {nullptr, nullptr};
    int wi = 0, bi = 0;
    for (int i = 0; i < n_in; i++) {
        int sz = in_sizes[i];
        if (sz == NN * D)            x = (const float*)d_in[i];
        else if (sz == NN * 3)       ei = (const int*)d_in[i];
        else if (sz == D * D)        { if (wi < 2) W[wi++] = (const float*)d_in[i]; }
        else if (sz == D)            { if (bi < 2) b[bi++] = (const float*)d_in[i]; }
    }
    const float* W1 = W[0]; const float* b1 = b[0];
    const float* W2 = W[1]; const float* b2 = b[1];
    float* out = (float*)d_out;

    void *p1, *p2;
    cudaGetSymbolAddress(&p1, g_buf1);
    cudaGetSymbolAddress(&p2, g_buf2);
    float* buf1 = (float*)p1;
    float* buf2 = (float*)p2;

    // 1. degree
    deg_kernel<<<(NN + 255) / 256, 256>>>(ei);

    dim3 ggrid(D / 128, (NN + 127) / 128);  // (4, 782)

    // 2. layer 1 GEMM: h1 = (x @ W1^T + b1) * rsd  -> buf1
    gemm_kernel<<<ggrid, 256>>>(x, W1, b1, buf1);
    // 3. layer 1 aggregate + ELU -> buf2
    agg_kernel<<<NN, 128>>>(buf1, ei, buf2);
    // 4. layer 2 GEMM -> buf1
    gemm_kernel<<<ggrid, 256>>>(buf2, W2, b2, buf1);
    // 5. layer 2 aggregate + ELU -> d_out
    agg_kernel<<<NN, 128>>>(buf1, ei, out);
}

// round 4
// speedup vs baseline: 2.0118x; 2.0118x over previous
#include <cuda_runtime.h>
#include <cuda_bf16.h>
#include <cstdint>

#define NN 100000
#define D  512

// Scratch (allocation-free rule: __device__ globals)
__device__ __align__(128) float g_buf1[(size_t)NN * D];
__device__ __align__(128) float g_buf2[(size_t)NN * D];
__device__ float g_rsd[NN];

static __device__ __forceinline__ uint32_t smem_u32(const void* p) {
    uint32_t a;
    asm("{ .reg .u64 t; cvta.to.shared.u64 t, %1; cvt.u32.u64 %0, t; }" : "=r"(a) : "l"(p));
    return a;
}

// ldmatrix x4 (non-trans): 4 8x8 b16 tiles, lane-group q provides tile q's row addrs
#define LDSM4(r, addr) \
    asm volatile("ldmatrix.sync.aligned.m8n8.x4.shared.b16 {%0,%1,%2,%3}, [%4];" \
        : "=r"((r)[0]), "=r"((r)[1]), "=r"((r)[2]), "=r"((r)[3]) : "r"(addr))

// D += A x B  (m16n8k16, bf16 in, f32 acc)
#define MMA16816(d, a, b0, b1) \
    asm volatile("mma.sync.aligned.m16n8k16.row.col.f32.bf16.bf16.f32 " \
        "{%0,%1,%2,%3}, {%4,%5,%6,%7}, {%8,%9}, {%0,%1,%2,%3};" \
        : "+f"((d)[0]), "+f"((d)[1]), "+f"((d)[2]), "+f"((d)[3]) \
        : "r"((a)[0]), "r"((a)[1]), "r"((a)[2]), "r"((a)[3]), "r"(b0), "r"(b1))

// fp32 pair -> bf16 hi/lo split (packed bf16x2 words)
static __device__ __forceinline__ void split2(float x, float y, uint32_t& h, uint32_t& l) {
    __nv_bfloat162 hb = __floats2bfloat162_rn(x, y);
    float hx = __low2float(hb), hy = __high2float(hb);
    __nv_bfloat162 lb = __floats2bfloat162_rn(x - hx, y - hy);
    h = *reinterpret_cast<uint32_t*>(&hb);
    l = *reinterpret_cast<uint32_t*>(&lb);
}

__global__ void deg_kernel(const int* __restrict__ ei) {
    int i = blockIdx.x * blockDim.x + threadIdx.x;
    if (i >= NN) return;
    int c = 1;
#pragma unroll
    for (int j = 0; j < 3; j++) c += (ei[i * 3 + j] >= 0);
    g_rsd[i] = rsqrtf((float)c);
}

// ---------------- HMMA GEMM: C[m,n] = (sum_k A[m,k]*W[n,k] + bias[n]) * rsd[m] ----
// Block 128x128, K-chunk 32. SMEM tile per stage: A[128 rows][128B] where row =
// {hi chunks 0..3 | lo chunks 4..7}, 16B chunk stored at slot (chunk ^ (row&7)).
// W tile identical at +16384. Double buffered.
static constexpr int STAGE_BYTES = 32768;
static constexpr int SMEM_TOTAL  = 1024 + 2 * STAGE_BYTES;

__global__ void __launch_bounds__(256, 1)
gemm_hmma(const float* __restrict__ A, const float* __restrict__ W,
          const float* __restrict__ bias, float* __restrict__ C) {
    extern __shared__ char smem[];
    const int tid = threadIdx.x, lid = tid & 31, wid = tid >> 5;
    const int m0 = blockIdx.y * 128, n0 = blockIdx.x * 128;

    float* biasS = (float*)smem;
    if (tid < 128) biasS[tid] = bias[n0 + tid];

    // loader role: thread -> (row 0..127, half 0..1): 16 fp32 per chunk
    const int lrow = tid >> 1, lh = tid & 1;
    const bool aval = (m0 + lrow) < NN;
    const float* aG = A + (size_t)(m0 + lrow) * D + lh * 16;
    const float* wG = W + (size_t)(n0 + lrow) * D + lh * 16;
    const int s0 = (((2 * lh) ^ (lrow & 7)) << 4);  // hi chunk-0 slot byte offset

    const uint32_t sb = smem_u32(smem);

    float4 ra[4], rw[4];
    float acc[2][8][4];
#pragma unroll
    for (int mt = 0; mt < 2; mt++)
#pragma unroll
        for (int nt = 0; nt < 8; nt++)
#pragma unroll
            for (int j = 0; j < 4; j++) acc[mt][nt][j] = 0.f;

    auto ldg = [&](int c) {
        const int kc = c * 32;
#pragma unroll
        for (int i = 0; i < 4; i++) {
            ra[i] = aval ? *(const float4*)(aG + kc + i * 4) : make_float4(0.f, 0.f, 0.f, 0.f);
            rw[i] = *(const float4*)(wG + kc + i * 4);
        }
    };

    auto sts = [&](int stage) {
        const float* fa = (const float*)ra;
        const float* fw = (const float*)rw;
        uint32_t ha[8], la[8], hw[8], lw[8];
#pragma unroll
        for (int j = 0; j < 8; j++) {
            split2(fa[2 * j], fa[2 * j + 1], ha[j], la[j]);
            split2(fw[2 * j], fw[2 * j + 1], hw[j], lw[j]);
        }
        char* rb = smem + 1024 + stage * STAGE_BYTES + lrow * 128;
        *(uint4*)(rb + s0)        = make_uint4(ha[0], ha[1], ha[2], ha[3]);
        *(uint4*)(rb + (s0 ^ 16)) = make_uint4(ha[4], ha[5], ha[6], ha[7]);
        *(uint4*)(rb + (s0 ^ 64)) = make_uint4(la[0], la[1], la[2], la[3]);
        *(uint4*)(rb + (s0 ^ 80)) = make_uint4(la[4], la[5], la[6], la[7]);
        char* wb = rb + 16384;
        *(uint4*)(wb + s0)        = make_uint4(hw[0], hw[1], hw[2], hw[3]);
        *(uint4*)(wb + (s0 ^ 16)) = make_uint4(hw[4], hw[5], hw[6], hw[7]);
        *(uint4*)(wb + (s0 ^ 64)) = make_uint4(lw[0], lw[1], lw[2], lw[3]);
        *(uint4*)(wb + (s0 ^ 80)) = make_uint4(lw[4], lw[5], lw[6], lw[7]);
    };

    const int mbase = (wid & 3) * 32, nbase = (wid >> 2) * 64;
    const int q = lid >> 3, rr = lid & 7;

    auto compute = [&](int stage) {
        const uint32_t aT = sb + 1024 + stage * STAGE_BYTES;
        const uint32_t wT = aT + 16384;
#pragma unroll
        for (int ks = 0; ks < 2; ks++) {
            uint32_t ah[2][4], al[2][4];
#pragma unroll
            for (int mt = 0; mt < 2; mt++) {
                int row = mbase + mt * 16 + (q & 1) * 8 + rr;
                int ch  = 2 * ks + (q >> 1);
                uint32_t ad = aT + row * 128 + ((ch ^ (row & 7)) << 4);
                LDSM4(ah[mt], ad);
                LDSM4(al[mt], ad ^ 64);
            }
            uint32_t bh[4][4], bl[4][4];
#pragma unroll
            for (int p = 0; p < 4; p++) {
                int nrow = nbase + p * 16 + (q >> 1) * 8 + rr;
                int ch   = 2 * ks + (q & 1);
                uint32_t bd = wT + nrow * 128 + ((ch ^ (nrow & 7)) << 4);
                LDSM4(bh[p], bd);
                LDSM4(bl[p], bd ^ 64);
            }
#pragma unroll
            for (int mt = 0; mt < 2; mt++)
#pragma unroll
                for (int nt = 0; nt < 8; nt++) {
                    uint32_t b0h = bh[nt >> 1][(nt & 1) * 2], b1h = bh[nt >> 1][(nt & 1) * 2 + 1];
                    uint32_t b0l = bl[nt >> 1][(nt & 1) * 2], b1l = bl[nt >> 1][(nt & 1) * 2 + 1];
                    MMA16816(acc[mt][nt], ah[mt], b0h, b1h);
                    MMA16816(acc[mt][nt], al[mt], b0h, b1h);
                    MMA16816(acc[mt][nt], ah[mt], b0l, b1l);
                }
        }
    };

    // pipeline: prefetch chunk c+1 in regs while computing chunk c
    ldg(0);
    sts(0);
    __syncthreads();
#pragma unroll 1
    for (int c = 0; c < 16; c++) {
        if (c < 15) ldg(c + 1);
        compute(c & 1);
        if (c < 15) {
            sts((c + 1) & 1);
            __syncthreads();
        }
    }

    // epilogue: (acc + bias) * rsd
#pragma unroll
    for (int mt = 0; mt < 2; mt++)
#pragma unroll
        for (int half = 0; half < 2; half++) {
            int row = m0 + mbase + mt * 16 + (lid >> 2) + half * 8;
            if (row < NN) {
                float rs = g_rsd[row];
#pragma unroll
                for (int nt = 0; nt < 8; nt++) {
                    int colrel = nbase + nt * 8 + (lid & 3) * 2;
                    float2 v;
                    v.x = (acc[mt][nt][half * 2 + 0] + biasS[colrel + 0]) * rs;
                    v.y = (acc[mt][nt][half * 2 + 1] + biasS[colrel + 1]) * rs;
                    *(float2*)(C + (size_t)row * D + n0 + colrel) = v;
                }
            }
        }
}

// ---------- aggregation: out[i] = elu((h[i] + sum_valid h[e]) * rsd[i]) ----------
__global__ void agg_kernel(const float* __restrict__ h,
                           const int* __restrict__ ei,
                           float* __restrict__ out) {
    const size_t node = blockIdx.x;
    const int t = threadIdx.x;
    const float4* hv = (const float4*)h;

    float4 acc = hv[node * 128 + t];
    int e0 = ei[node * 3 + 0];
    int e1 = ei[node * 3 + 1];
    int e2 = ei[node * 3 + 2];
    if (e0 >= 0) { float4 v = hv[(size_t)e0 * 128 + t]; acc.x += v.x; acc.y += v.y; acc.z += v.z; acc.w += v.w; }
    if (e1 >= 0) { float4 v = hv[(size_t)e1 * 128 + t]; acc.x += v.x; acc.y += v.y; acc.z += v.z; acc.w += v.w; }
    if (e2 >= 0) { float4 v = hv[(size_t)e2 * 128 + t]; acc.x += v.x; acc.y += v.y; acc.z += v.z; acc.w += v.w; }

    const float rs = g_rsd[node];
    acc.x *= rs; acc.y *= rs; acc.z *= rs; acc.w *= rs;
    acc.x = acc.x > 0.f ? acc.x : expm1f(acc.x);
    acc.y = acc.y > 0.f ? acc.y : expm1f(acc.y);
    acc.z = acc.z > 0.f ? acc.z : expm1f(acc.z);
    acc.w = acc.w > 0.f ? acc.w : expm1f(acc.w);

    ((float4*)out)[node * 128 + t] = acc;
}

extern "C" void kernel_launch(void* const* d_in, const int* in_sizes, int n_in,
                              void* d_out, int out_size) {
    const float* x  = nullptr;
    const int*   ei = nullptr;
    const float* Wt[2] = {nullptr, nullptr};
    const float* bt[2] = {nullptr, nullptr};
    int wi = 0, bi = 0;
    for (int i = 0; i < n_in; i++) {
        int sz = in_sizes[i];
        if (sz == NN * D)      x = (const float*)d_in[i];
        else if (sz == NN * 3) ei = (const int*)d_in[i];
        else if (sz == D * D)  { if (wi < 2) Wt[wi++] = (const float*)d_in[i]; }
        else if (sz == D)      { if (bi < 2) bt[bi++] = (const float*)d_in[i]; }
    }
    float* out = (float*)d_out;

    void *p1, *p2;
    cudaGetSymbolAddress(&p1, g_buf1);
    cudaGetSymbolAddress(&p2, g_buf2);
    float* buf1 = (float*)p1;
    float* buf2 = (float*)p2;

    // >48KB dynamic smem opt-in (sticky per function; first call is uncaptured)
    cudaFuncSetAttribute(gemm_hmma, cudaFuncAttributeMaxDynamicSharedMemorySize, SMEM_TOTAL);

    deg_kernel<<<(NN + 255) / 256, 256>>>(ei);

    dim3 ggrid(D / 128, (NN + 127) / 128);  // (4, 782)
    gemm_hmma<<<ggrid, 256, SMEM_TOTAL>>>(x, Wt[0], bt[0], buf1);
    agg_kernel<<<NN, 128>>>(buf1, ei, buf2);
    gemm_hmma<<<ggrid, 256, SMEM_TOTAL>>>(buf2, Wt[1], bt[1], buf1);
    agg_kernel<<<NN, 128>>>(buf1, ei, out);
}

// round 5
// speedup vs baseline: 2.2230x; 1.1050x over previous
#include <cuda_runtime.h>
#include <cuda_bf16.h>
#include <cstdint>

#define NN 100000
#define D  512

// Scratch (allocation-free rule: __device__ globals)
__device__ __align__(128) float g_h[(size_t)NN * D];
__device__ __align__(128) __nv_bfloat16 g_ahi[(size_t)NN * D];
__device__ __align__(128) __nv_bfloat16 g_alo[(size_t)NN * D];
__device__ __align__(128) __nv_bfloat16 g_w1hi[D * D], g_w1lo[D * D];
__device__ __align__(128) __nv_bfloat16 g_w2hi[D * D], g_w2lo[D * D];
__device__ float g_rsd[NN];

static __device__ __forceinline__ uint32_t smem_u32(const void* p) {
    uint32_t a;
    asm("{ .reg .u64 t; cvta.to.shared.u64 t, %1; cvt.u32.u64 %0, t; }" : "=r"(a) : "l"(p));
    return a;
}

#define LDSM4(r, addr) \
    asm volatile("ldmatrix.sync.aligned.m8n8.x4.shared.b16 {%0,%1,%2,%3}, [%4];" \
        : "=r"((r)[0]), "=r"((r)[1]), "=r"((r)[2]), "=r"((r)[3]) : "r"(addr))

#define MMA16816(d, a, b0, b1) \
    asm volatile("mma.sync.aligned.m16n8k16.row.col.f32.bf16.bf16.f32 " \
        "{%0,%1,%2,%3}, {%4,%5,%6,%7}, {%8,%9}, {%0,%1,%2,%3};" \
        : "+f"((d)[0]), "+f"((d)[1]), "+f"((d)[2]), "+f"((d)[3]) \
        : "r"((a)[0]), "r"((a)[1]), "r"((a)[2]), "r"((a)[3]), "r"(b0), "r"(b1))

// cp.async 16B with zfill predicate (n = 16 or 0)
#define CP16(dst, src, n) \
    asm volatile("cp.async.cg.shared.global [%0], [%1], 16, %2;" \
        :: "r"(dst), "l"(src), "r"(n))
#define CP_COMMIT() asm volatile("cp.async.commit_group;" ::: "memory")
#define CP_WAIT1()  asm volatile("cp.async.wait_group 1;" ::: "memory")

static __device__ __forceinline__ void split2(float x, float y, uint32_t& h, uint32_t& l) {
    __nv_bfloat162 hb = __floats2bfloat162_rn(x, y);
    float hx = __low2float(hb), hy = __high2float(hb);
    __nv_bfloat162 lb = __floats2bfloat162_rn(x - hx, y - hy);
    h = *reinterpret_cast<uint32_t*>(&hb);
    l = *reinterpret_cast<uint32_t*>(&lb);
}

__global__ void deg_kernel(const int* __restrict__ ei) {
    int i = blockIdx.x * blockDim.x + threadIdx.x;
    if (i >= NN) return;
    int c = 1;
#pragma unroll
    for (int j = 0; j < 3; j++) c += (ei[i * 3 + j] >= 0);
    g_rsd[i] = rsqrtf((float)c);
}

// fp32 -> bf16 hi/lo arrays (vectorized float4 -> 2x uint2)
__global__ void split_kernel(const float* __restrict__ src,
                             __nv_bfloat16* __restrict__ hi,
                             __nv_bfloat16* __restrict__ lo, int n4) {
    int i = blockIdx.x * blockDim.x + threadIdx.x;
    if (i >= n4) return;
    float4 v = ((const float4*)src)[i];
    uint32_t h0, l0, h1, l1;
    split2(v.x, v.y, h0, l0);
    split2(v.z, v.w, h1, l1);
    ((uint2*)hi)[i] = make_uint2(h0, h1);
    ((uint2*)lo)[i] = make_uint2(l0, l1);
}

// ---------------- bf16 pre-split HMMA GEMM ----------------
// Block 128x128, K-chunk 32. SMEM row r (128B) = 8 x 16B slots: logical slot
// s (<4: hi k-chunk s, >=4: lo k-chunk s-4) stored at phys slot s^(r&7).
// A tile 16KB + B tile 16KB per stage, 3 stages, cp.async pipeline.
static constexpr int STAGE_BYTES = 32768;
static constexpr int NSTAGE = 3;
static constexpr int SMEM_TOTAL = 1024 + NSTAGE * STAGE_BYTES;

__global__ void __launch_bounds__(256, 2)
gemm_hmma(const __nv_bfloat16* __restrict__ Ahi, const __nv_bfloat16* __restrict__ Alo,
          const __nv_bfloat16* __restrict__ Whi, const __nv_bfloat16* __restrict__ Wlo,
          const float* __restrict__ bias, float* __restrict__ C) {
    extern __shared__ char smem[];
    const int tid = threadIdx.x, lid = tid & 31, wid = tid >> 5;
    const int m0 = blockIdx.y * 128, n0 = blockIdx.x * 128;

    float* biasS = (float*)smem;
    if (tid < 128) biasS[tid] = bias[n0 + tid];
    const uint32_t sb = smem_u32(smem) + 1024;

    // loader role: 2 threads per row, thread h covers k [16h..16h+16) of each chunk
    const int r = tid >> 1, h = tid & 1;
    const bool aval = (m0 + r) < NN;
    const int pa = aval ? 16 : 0;
    const __nv_bfloat16* aHsrc = Ahi + (size_t)(m0 + (aval ? r : 0)) * D + h * 16;
    const __nv_bfloat16* aLsrc = Alo + (size_t)(m0 + (aval ? r : 0)) * D + h * 16;
    const __nv_bfloat16* bHsrc = Whi + (size_t)(n0 + r) * D + h * 16;
    const __nv_bfloat16* bLsrc = Wlo + (size_t)(n0 + r) * D + h * 16;
    const uint32_t rowA = sb + r * 128;
    const uint32_t rowB = sb + 16384 + r * 128;
    const uint32_t sH0 = (uint32_t)(((2 * h)     ^ (r & 7)) << 4);
    const uint32_t sH1 = (uint32_t)(((2 * h + 1) ^ (r & 7)) << 4);
    const uint32_t sL0 = (uint32_t)(((4 + 2 * h) ^ (r & 7)) << 4);
    const uint32_t sL1 = (uint32_t)(((5 + 2 * h) ^ (r & 7)) << 4);

    float acc[2][8][4];
#pragma unroll
    for (int mt = 0; mt < 2; mt++)
#pragma unroll
        for (int nt = 0; nt < 8; nt++)
#pragma unroll
            for (int j = 0; j < 4; j++) acc[mt][nt][j] = 0.f;

    auto issue = [&](int c) {
        const int st = c % NSTAGE;
        const uint32_t dA = rowA + st * STAGE_BYTES;
        const uint32_t dB = rowB + st * STAGE_BYTES;
        const int ko = c * 32;
        CP16(dA + sH0, aHsrc + ko,     pa);
        CP16(dA + sH1, aHsrc + ko + 8, pa);
        CP16(dA + sL0, aLsrc + ko,     pa);
        CP16(dA + sL1, aLsrc + ko + 8, pa);
        CP16(dB + sH0, bHsrc + ko,     16);
        CP16(dB + sH1, bHsrc + ko + 8, 16);
        CP16(dB + sL0, bLsrc + ko,     16);
        CP16(dB + sL1, bLsrc + ko + 8, 16);
    };

    const int mbase = (wid & 3) * 32, nbase = (wid >> 2) * 64;
    const int q = lid >> 3, rr = lid & 7;

    auto compute = [&](int st) {
        const uint32_t aT = sb + st * STAGE_BYTES;
        const uint32_t wT = aT + 16384;
#pragma unroll
        for (int ks = 0; ks < 2; ks++) {
            uint32_t ah[2][4], al[2][4];
#pragma unroll
            for (int mt = 0; mt < 2; mt++) {
                int row = mbase + mt * 16 + (q & 1) * 8 + rr;
                int ch  = 2 * ks + (q >> 1);
                uint32_t ad = aT + row * 128 + ((ch ^ (row & 7)) << 4);
                LDSM4(ah[mt], ad);
                LDSM4(al[mt], ad ^ 64);
            }
#pragma unroll
            for (int p = 0; p < 4; p++) {
                uint32_t bh[4], bl[4];
                int nrow = nbase + p * 16 + (q >> 1) * 8 + rr;
                int ch   = 2 * ks + (q & 1);
                uint32_t bd = wT + nrow * 128 + ((ch ^ (nrow & 7)) << 4);
                LDSM4(bh, bd);
                LDSM4(bl, bd ^ 64);
#pragma unroll
                for (int mt = 0; mt < 2; mt++)
#pragma unroll
                    for (int j = 0; j < 2; j++) {
                        float* d = acc[mt][2 * p + j];
                        MMA16816(d, ah[mt], bh[2 * j], bh[2 * j + 1]);
                        MMA16816(d, al[mt], bh[2 * j], bh[2 * j + 1]);
                        MMA16816(d, ah[mt], bl[2 * j], bl[2 * j + 1]);
                    }
            }
        }
    };

    // prologue: stages 0 and 1 in flight
    issue(0); CP_COMMIT();
    issue(1); CP_COMMIT();

#pragma unroll 1
    for (int c = 0; c < 16; c++) {
        CP_WAIT1();          // stage c complete
        __syncthreads();
        if (c + 2 < 16) issue(c + 2);
        CP_COMMIT();         // (possibly empty) keeps group count uniform
        compute(c % NSTAGE);
    }

    // epilogue: (acc + bias) * rsd
#pragma unroll
    for (int mt = 0; mt < 2; mt++)
#pragma unroll
        for (int half = 0; half < 2; half++) {
            int row = m0 + mbase + mt * 16 + (lid >> 2) + half * 8;
            if (row < NN) {
                float rs = g_rsd[row];
#pragma unroll
                for (int nt = 0; nt < 8; nt++) {
                    int colrel = nbase + nt * 8 + (lid & 3) * 2;
                    float2 v;
                    v.x = (acc[mt][nt][half * 2 + 0] + biasS[colrel + 0]) * rs;
                    v.y = (acc[mt][nt][half * 2 + 1] + biasS[colrel + 1]) * rs;
                    *(float2*)(C + (size_t)row * D + n0 + colrel) = v;
                }
            }
        }
}

// ---------- aggregation + ELU, output split to bf16 hi/lo (feeds next GEMM) ----
__global__ void agg_split_kernel(const float* __restrict__ h,
                                 const int* __restrict__ ei,
                                 __nv_bfloat16* __restrict__ hi,
                                 __nv_bfloat16* __restrict__ lo) {
    const size_t node = blockIdx.x;
    const int t = threadIdx.x;
    const float4* hv = (const float4*)h;

    float4 acc = hv[node * 128 + t];
    int e0 = ei[node * 3 + 0];
    int e1 = ei[node * 3 + 1];
    int e2 = ei[node * 3 + 2];
    if (e0 >= 0) { float4 v = hv[(size_t)e0 * 128 + t]; acc.x += v.x; acc.y += v.y; acc.z += v.z; acc.w += v.w; }
    if (e1 >= 0) { float4 v = hv[(size_t)e1 * 128 + t]; acc.x += v.x; acc.y += v.y; acc.z += v.z; acc.w += v.w; }
    if (e2 >= 0) { float4 v = hv[(size_t)e2 * 128 + t]; acc.x += v.x; acc.y += v.y; acc.z += v.z; acc.w += v.w; }

    const float rs = g_rsd[node];
    acc.x *= rs; acc.y *= rs; acc.z *= rs; acc.w *= rs;
    acc.x = acc.x > 0.f ? acc.x : expm1f(acc.x);
    acc.y = acc.y > 0.f ? acc.y : expm1f(acc.y);
    acc.z = acc.z > 0.f ? acc.z : expm1f(acc.z);
    acc.w = acc.w > 0.f ? acc.w : expm1f(acc.w);

    uint32_t h0, l0, h1, l1;
    split2(acc.x, acc.y, h0, l0);
    split2(acc.z, acc.w, h1, l1);
    ((uint2*)hi)[node * 128 + t] = make_uint2(h0, h1);
    ((uint2*)lo)[node * 128 + t] = make_uint2(l0, l1);
}

// ---------- final aggregation + ELU, fp32 out ----------
__global__ void agg_kernel(const float* __restrict__ h,
                           const int* __restrict__ ei,
                           float* __restrict__ out) {
    const size_t node = blockIdx.x;
    const int t = threadIdx.x;
    const float4* hv = (const float4*)h;

    float4 acc = hv[node * 128 + t];
    int e0 = ei[node * 3 + 0];
    int e1 = ei[node * 3 + 1];
    int e2 = ei[node * 3 + 2];
    if (e0 >= 0) { float4 v = hv[(size_t)e0 * 128 + t]; acc.x += v.x; acc.y += v.y; acc.z += v.z; acc.w += v.w; }
    if (e1 >= 0) { float4 v = hv[(size_t)e1 * 128 + t]; acc.x += v.x; acc.y += v.y; acc.z += v.z; acc.w += v.w; }
    if (e2 >= 0) { float4 v = hv[(size_t)e2 * 128 + t]; acc.x += v.x; acc.y += v.y; acc.z += v.z; acc.w += v.w; }

    const float rs = g_rsd[node];
    acc.x *= rs; acc.y *= rs; acc.z *= rs; acc.w *= rs;
    acc.x = acc.x > 0.f ? acc.x : expm1f(acc.x);
    acc.y = acc.y > 0.f ? acc.y : expm1f(acc.y);
    acc.z = acc.z > 0.f ? acc.z : expm1f(acc.z);
    acc.w = acc.w > 0.f ? acc.w : expm1f(acc.w);

    ((float4*)out)[node * 128 + t] = acc;
}

extern "C" void kernel_launch(void* const* d_in, const int* in_sizes, int n_in,
                              void* d_out, int out_size) {
    const float* x  = nullptr;
    const int*   ei = nullptr;
    const float* Wt[2] = {nullptr, nullptr};
    const float* bt[2] = {nullptr, nullptr};
    int wi = 0, bi = 0;
    for (int i = 0; i < n_in; i++) {
        int sz = in_sizes[i];
        if (sz == NN * D)      x = (const float*)d_in[i];
        else if (sz == NN * 3) ei = (const int*)d_in[i];
        else if (sz == D * D)  { if (wi < 2) Wt[wi++] = (const float*)d_in[i]; }
        else if (sz == D)      { if (bi < 2) bt[bi++] = (const float*)d_in[i]; }
    }
    float* out = (float*)d_out;

    void *ph, *pah, *pal, *pw1h, *pw1l, *pw2h, *pw2l;
    cudaGetSymbolAddress(&ph,  g_h);
    cudaGetSymbolAddress(&pah, g_ahi);
    cudaGetSymbolAddress(&pal, g_alo);
    cudaGetSymbolAddress(&pw1h, g_w1hi);
    cudaGetSymbolAddress(&pw1l, g_w1lo);
    cudaGetSymbolAddress(&pw2h, g_w2hi);
    cudaGetSymbolAddress(&pw2l, g_w2lo);
    float* hbuf = (float*)ph;
    __nv_bfloat16 *ahi = (__nv_bfloat16*)pah, *alo = (__nv_bfloat16*)pal;
    __nv_bfloat16 *w1hi = (__nv_bfloat16*)pw1h, *w1lo = (__nv_bfloat16*)pw1l;
    __nv_bfloat16 *w2hi = (__nv_bfloat16*)pw2h, *w2lo = (__nv_bfloat16*)pw2l;

    cudaFuncSetAttribute(gemm_hmma, cudaFuncAttributeMaxDynamicSharedMemorySize, SMEM_TOTAL);

    deg_kernel<<<(NN + 255) / 256, 256>>>(ei);
    split_kernel<<<(NN * D / 4 + 255) / 256, 256>>>(x, ahi, alo, NN * D / 4);
    split_kernel<<<(D * D / 4 + 255) / 256, 256>>>(Wt[0], w1hi, w1lo, D * D / 4);
    split_kernel<<<(D * D / 4 + 255) / 256, 256>>>(Wt[1], w2hi, w2lo, D * D / 4);

    dim3 ggrid(D / 128, (NN + 127) / 128);  // (4, 782)
    gemm_hmma<<<ggrid, 256, SMEM_TOTAL>>>(ahi, alo, w1hi, w1lo, bt[0], hbuf);
    agg_split_kernel<<<NN, 128>>>(hbuf, ei, ahi, alo);
    gemm_hmma<<<ggrid, 256, SMEM_TOTAL>>>(ahi, alo, w2hi, w2lo, bt[1], hbuf);
    agg_kernel<<<NN, 128>>>(hbuf, ei, out);
}

// round 6
// speedup vs baseline: 2.9007x; 1.3049x over previous
#include <cuda_runtime.h>
#include <cuda_fp16.h>
#include <cstdint>

#define NN 100000
#define D  512

// Scratch (allocation-free rule: __device__ globals)
__device__ __align__(128) float g_h[(size_t)NN * D];
__device__ __align__(128) __half g_ahi[(size_t)NN * D];
__device__ __align__(128) __half g_w1hi[D * D], g_w1lo[D * D];
__device__ __align__(128) __half g_w2hi[D * D], g_w2lo[D * D];
__device__ float g_rsd[NN];

static __device__ __forceinline__ uint32_t smem_u32(const void* p) {
    uint32_t a;
    asm("{ .reg .u64 t; cvta.to.shared.u64 t, %1; cvt.u32.u64 %0, t; }" : "=r"(a) : "l"(p));
    return a;
}

#define LDSM4(r, addr) \
    asm volatile("ldmatrix.sync.aligned.m8n8.x4.shared.b16 {%0,%1,%2,%3}, [%4];" \
        : "=r"((r)[0]), "=r"((r)[1]), "=r"((r)[2]), "=r"((r)[3]) : "r"(addr))

#define MMA16816(d, a, b0, b1) \
    asm volatile("mma.sync.aligned.m16n8k16.row.col.f32.f16.f16.f32 " \
        "{%0,%1,%2,%3}, {%4,%5,%6,%7}, {%8,%9}, {%0,%1,%2,%3};" \
        : "+f"((d)[0]), "+f"((d)[1]), "+f"((d)[2]), "+f"((d)[3]) \
        : "r"((a)[0]), "r"((a)[1]), "r"((a)[2]), "r"((a)[3]), "r"(b0), "r"(b1))

#define CP16(dst, src, n) \
    asm volatile("cp.async.cg.shared.global [%0], [%1], 16, %2;" \
        :: "r"(dst), "l"(src), "r"(n))
#define CP_COMMIT() asm volatile("cp.async.commit_group;" ::: "memory")
#define CP_WAIT1()  asm volatile("cp.async.wait_group 1;" ::: "memory")

// fp32 pair -> fp16 hi/lo split (packed half2 words)
static __device__ __forceinline__ void split2h(float x, float y, uint32_t& h, uint32_t& l) {
    __half2 hb = __floats2half2_rn(x, y);
    float hx = __low2float(hb), hy = __high2float(hb);
    __half2 lb = __floats2half2_rn(x - hx, y - hy);
    h = *reinterpret_cast<uint32_t*>(&hb);
    l = *reinterpret_cast<uint32_t*>(&lb);
}

__global__ void deg_kernel(const int* __restrict__ ei) {
    int i = blockIdx.x * blockDim.x + threadIdx.x;
    if (i >= NN) return;
    int c = 1;
#pragma unroll
    for (int j = 0; j < 3; j++) c += (ei[i * 3 + j] >= 0);
    g_rsd[i] = rsqrtf((float)c);
}

// fp32 -> fp16 hi only (for activations)
__global__ void tohalf_kernel(const float* __restrict__ src,
                              __half* __restrict__ hi, int n4) {
    int i = blockIdx.x * blockDim.x + threadIdx.x;
    if (i >= n4) return;
    float4 v = ((const float4*)src)[i];
    __half2 a = __floats2half2_rn(v.x, v.y);
    __half2 b = __floats2half2_rn(v.z, v.w);
    ((uint2*)hi)[i] = make_uint2(*(uint32_t*)&a, *(uint32_t*)&b);
}

// fp32 -> fp16 hi/lo (for weights)
__global__ void split_kernel(const float* __restrict__ src,
                             __half* __restrict__ hi,
                             __half* __restrict__ lo, int n4) {
    int i = blockIdx.x * blockDim.x + threadIdx.x;
    if (i >= n4) return;
    float4 v = ((const float4*)src)[i];
    uint32_t h0, l0, h1, l1;
    split2h(v.x, v.y, h0, l0);
    split2h(v.z, v.w, h1, l1);
    ((uint2*)hi)[i] = make_uint2(h0, h1);
    ((uint2*)lo)[i] = make_uint2(l0, l1);
}

// ---------------- fp16 2-term HMMA GEMM ----------------
// C[m,n] = (sum_k A[m,k]*(Whi[n,k]+Wlo[n,k]) + bias[n]) * rsd[m]
// Block 128x128, K-chunk 64, 2-stage cp.async pipeline.
// Stage: Ahi[128x128B] @0, Whi @16K, Wlo @32K. Row r = 8 x 16B slots,
// logical slot s (k [8s..8s+8)) stored at phys slot s^(r&7).
static constexpr int STAGE_BYTES = 49152;
static constexpr int SMEM_TOTAL  = 1024 + 2 * STAGE_BYTES;

__global__ void __launch_bounds__(256, 2)
gemm_hmma(const __half* __restrict__ Ahi,
          const __half* __restrict__ Whi, const __half* __restrict__ Wlo,
          const float* __restrict__ bias, float* __restrict__ C) {
    extern __shared__ char smem[];
    const int tid = threadIdx.x, lid = tid & 31, wid = tid >> 5;
    const int m0 = blockIdx.y * 128, n0 = blockIdx.x * 128;

    float* biasS = (float*)smem;
    if (tid < 128) biasS[tid] = bias[n0 + tid];
    const uint32_t sb = smem_u32(smem) + 1024;

    // loader role: 2 threads per row; thread h covers slots 4h..4h+3
    const int r = tid >> 1, h = tid & 1;
    const bool aval = (m0 + r) < NN;
    const int pa = aval ? 16 : 0;
    const __half* aSrc = Ahi + (size_t)(m0 + (aval ? r : 0)) * D;
    const __half* bHs  = Whi + (size_t)(n0 + r) * D;
    const __half* bLs  = Wlo + (size_t)(n0 + r) * D;

    float acc[2][8][4];
#pragma unroll
    for (int mt = 0; mt < 2; mt++)
#pragma unroll
        for (int nt = 0; nt < 8; nt++)
#pragma unroll
            for (int j = 0; j < 4; j++) acc[mt][nt][j] = 0.f;

    auto issue = [&](int c) {
        const int st = c & 1;
        const uint32_t dA = sb + st * STAGE_BYTES + r * 128;
        const int ko = c * 64;
#pragma unroll
        for (int j = 0; j < 4; j++) {
            const int s = 4 * h + j;
            const uint32_t so = (uint32_t)((s ^ (r & 7)) << 4);
            CP16(dA + so,         aSrc + ko + s * 8, pa);
            CP16(dA + 16384 + so, bHs  + ko + s * 8, 16);
            CP16(dA + 32768 + so, bLs  + ko + s * 8, 16);
        }
    };

    const int mbase = (wid & 3) * 32, nbase = (wid >> 2) * 64;
    const int q = lid >> 3, rr = lid & 7;

    auto compute = [&](int st) {
        const uint32_t aT = sb + st * STAGE_BYTES;
#pragma unroll
        for (int ks = 0; ks < 4; ks++) {
            uint32_t ah[2][4];
#pragma unroll
            for (int mt = 0; mt < 2; mt++) {
                int row = mbase + mt * 16 + (q & 1) * 8 + rr;
                int ch  = 2 * ks + (q >> 1);
                LDSM4(ah[mt], aT + row * 128 + ((ch ^ (row & 7)) << 4));
            }
#pragma unroll
            for (int p = 0; p < 4; p++) {
                uint32_t bh[4], bl[4];
                int nrow = nbase + p * 16 + (q >> 1) * 8 + rr;
                int ch   = 2 * ks + (q & 1);
                uint32_t off = (uint32_t)(nrow * 128 + ((ch ^ (nrow & 7)) << 4));
                LDSM4(bh, aT + 16384 + off);
                LDSM4(bl, aT + 32768 + off);
#pragma unroll
                for (int mt = 0; mt < 2; mt++)
#pragma unroll
                    for (int j = 0; j < 2; j++) {
                        float* d = acc[mt][2 * p + j];
                        MMA16816(d, ah[mt], bh[2 * j], bh[2 * j + 1]);
                        MMA16816(d, ah[mt], bl[2 * j], bl[2 * j + 1]);
                    }
            }
        }
    };

    issue(0); CP_COMMIT();
    issue(1); CP_COMMIT();

#pragma unroll 1
    for (int c = 0; c < 8; c++) {
        CP_WAIT1();           // stage c resident
        __syncthreads();
        compute(c & 1);
        __syncthreads();      // everyone done reading stage c&1
        if (c + 2 < 8) issue(c + 2);
        CP_COMMIT();          // uniform group count (may be empty)
    }

    // epilogue: (acc + bias) * rsd
#pragma unroll
    for (int mt = 0; mt < 2; mt++)
#pragma unroll
        for (int half = 0; half < 2; half++) {
            int row = m0 + mbase + mt * 16 + (lid >> 2) + half * 8;
            if (row < NN) {
                float rs = g_rsd[row];
#pragma unroll
                for (int nt = 0; nt < 8; nt++) {
                    int colrel = nbase + nt * 8 + (lid & 3) * 2;
                    float2 v;
                    v.x = (acc[mt][nt][half * 2 + 0] + biasS[colrel + 0]) * rs;
                    v.y = (acc[mt][nt][half * 2 + 1] + biasS[colrel + 1]) * rs;
                    *(float2*)(C + (size_t)row * D + n0 + colrel) = v;
                }
            }
        }
}

// ---------- aggregation + ELU, output fp16 hi (feeds next GEMM) ----------
__global__ void agg_half_kernel(const float* __restrict__ h,
                                const int* __restrict__ ei,
                                __half* __restrict__ hi) {
    const size_t node = blockIdx.x;
    const int t = threadIdx.x;
    const float4* hv = (const float4*)h;

    float4 acc = hv[node * 128 + t];
    int e0 = ei[node * 3 + 0];
    int e1 = ei[node * 3 + 1];
    int e2 = ei[node * 3 + 2];
    if (e0 >= 0) { float4 v = hv[(size_t)e0 * 128 + t]; acc.x += v.x; acc.y += v.y; acc.z += v.z; acc.w += v.w; }
    if (e1 >= 0) { float4 v = hv[(size_t)e1 * 128 + t]; acc.x += v.x; acc.y += v.y; acc.z += v.z; acc.w += v.w; }
    if (e2 >= 0) { float4 v = hv[(size_t)e2 * 128 + t]; acc.x += v.x; acc.y += v.y; acc.z += v.z; acc.w += v.w; }

    const float rs = g_rsd[node];
    acc.x *= rs; acc.y *= rs; acc.z *= rs; acc.w *= rs;
    acc.x = acc.x > 0.f ? acc.x : expm1f(acc.x);
    acc.y = acc.y > 0.f ? acc.y : expm1f(acc.y);
    acc.z = acc.z > 0.f ? acc.z : expm1f(acc.z);
    acc.w = acc.w > 0.f ? acc.w : expm1f(acc.w);

    __half2 a = __floats2half2_rn(acc.x, acc.y);
    __half2 b = __floats2half2_rn(acc.z, acc.w);
    ((uint2*)hi)[node * 128 + t] = make_uint2(*(uint32_t*)&a, *(uint32_t*)&b);
}

// ---------- final aggregation + ELU, fp32 out ----------
__global__ void agg_kernel(const float* __restrict__ h,
                           const int* __restrict__ ei,
                           float* __restrict__ out) {
    const size_t node = blockIdx.x;
    const int t = threadIdx.x;
    const float4* hv = (const float4*)h;

    float4 acc = hv[node * 128 + t];
    int e0 = ei[node * 3 + 0];
    int e1 = ei[node * 3 + 1];
    int e2 = ei[node * 3 + 2];
    if (e0 >= 0) { float4 v = hv[(size_t)e0 * 128 + t]; acc.x += v.x; acc.y += v.y; acc.z += v.z; acc.w += v.w; }
    if (e1 >= 0) { float4 v = hv[(size_t)e1 * 128 + t]; acc.x += v.x; acc.y += v.y; acc.z += v.z; acc.w += v.w; }
    if (e2 >= 0) { float4 v = hv[(size_t)e2 * 128 + t]; acc.x += v.x; acc.y += v.y; acc.z += v.z; acc.w += v.w; }

    const float rs = g_rsd[node];
    acc.x *= rs; acc.y *= rs; acc.z *= rs; acc.w *= rs;
    acc.x = acc.x > 0.f ? acc.x : expm1f(acc.x);
    acc.y = acc.y > 0.f ? acc.y : expm1f(acc.y);
    acc.z = acc.z > 0.f ? acc.z : expm1f(acc.z);
    acc.w = acc.w > 0.f ? acc.w : expm1f(acc.w);

    ((float4*)out)[node * 128 + t] = acc;
}

extern "C" void kernel_launch(void* const* d_in, const int* in_sizes, int n_in,
                              void* d_out, int out_size) {
    const float* x  = nullptr;
    const int*   ei = nullptr;
    const float* Wt[2] = {nullptr, nullptr};
    const float* bt[2] = {nullptr, nullptr};
    int wi = 0, bi = 0;
    for (int i = 0; i < n_in; i++) {
        int sz = in_sizes[i];
        if (sz == NN * D)      x = (const float*)d_in[i];
        else if (sz == NN * 3) ei = (const int*)d_in[i];
        else if (sz == D * D)  { if (wi < 2) Wt[wi++] = (const float*)d_in[i]; }
        else if (sz == D)      { if (bi < 2) bt[bi++] = (const float*)d_in[i]; }
    }
    float* out = (float*)d_out;

    void *ph, *pah, *pw1h, *pw1l, *pw2h, *pw2l;
    cudaGetSymbolAddress(&ph,  g_h);
    cudaGetSymbolAddress(&pah, g_ahi);
    cudaGetSymbolAddress(&pw1h, g_w1hi);
    cudaGetSymbolAddress(&pw1l, g_w1lo);
    cudaGetSymbolAddress(&pw2h, g_w2hi);
    cudaGetSymbolAddress(&pw2l, g_w2lo);
    float* hbuf = (float*)ph;
    __half* ahi = (__half*)pah;
    __half *w1hi = (__half*)pw1h, *w1lo = (__half*)pw1l;
    __half *w2hi = (__half*)pw2h, *w2lo = (__half*)pw2l;

    cudaFuncSetAttribute(gemm_hmma, cudaFuncAttributeMaxDynamicSharedMemorySize, SMEM_TOTAL);

    deg_kernel<<<(NN + 255) / 256, 256>>>(ei);
    tohalf_kernel<<<(NN * D / 4 + 255) / 256, 256>>>(x, ahi, NN * D / 4);
    split_kernel<<<(D * D / 4 + 255) / 256, 256>>>(Wt[0], w1hi, w1lo, D * D / 4);
    split_kernel<<<(D * D / 4 + 255) / 256, 256>>>(Wt[1], w2hi, w2lo, D * D / 4);

    dim3 ggrid(D / 128, (NN + 127) / 128);  // (4, 782)
    gemm_hmma<<<ggrid, 256, SMEM_TOTAL>>>(ahi, w1hi, w1lo, bt[0], hbuf);
    agg_half_kernel<<<NN, 128>>>(hbuf, ei, ahi);
    gemm_hmma<<<ggrid, 256, SMEM_TOTAL>>>(ahi, w2hi, w2lo, bt[1], hbuf);
    agg_kernel<<<NN, 128>>>(hbuf, ei, out);
}

// round 7
// speedup vs baseline: 3.0804x; 1.0620x over previous
#include <cuda_runtime.h>
#include <cuda_fp16.h>
#include <cstdint>

#define NN 100000
#define D  512

// Scratch (allocation-free rule: __device__ globals)
__device__ __align__(128) __half g_h[(size_t)NN * D];     // fp16 intermediate h
__device__ __align__(128) __half g_ahi[(size_t)NN * D];   // A operand for GEMM
__device__ __align__(128) __half g_w1hi[D * D], g_w1lo[D * D];
__device__ __align__(128) __half g_w2hi[D * D], g_w2lo[D * D];
__device__ float g_rsd[NN];

static __device__ __forceinline__ uint32_t smem_u32(const void* p) {
    uint32_t a;
    asm("{ .reg .u64 t; cvta.to.shared.u64 t, %1; cvt.u32.u64 %0, t; }" : "=r"(a) : "l"(p));
    return a;
}

#define LDSM4(r, addr) \
    asm volatile("ldmatrix.sync.aligned.m8n8.x4.shared.b16 {%0,%1,%2,%3}, [%4];" \
        : "=r"((r)[0]), "=r"((r)[1]), "=r"((r)[2]), "=r"((r)[3]) : "r"(addr))

#define MMA16816(d, a, b0, b1) \
    asm volatile("mma.sync.aligned.m16n8k16.row.col.f32.f16.f16.f32 " \
        "{%0,%1,%2,%3}, {%4,%5,%6,%7}, {%8,%9}, {%0,%1,%2,%3};" \
        : "+f"((d)[0]), "+f"((d)[1]), "+f"((d)[2]), "+f"((d)[3]) \
        : "r"((a)[0]), "r"((a)[1]), "r"((a)[2]), "r"((a)[3]), "r"(b0), "r"(b1))

#define CP16(dst, src, n) \
    asm volatile("cp.async.cg.shared.global [%0], [%1], 16, %2;" \
        :: "r"(dst), "l"(src), "r"(n))
#define CP_COMMIT() asm volatile("cp.async.commit_group;" ::: "memory")
#define CP_WAIT1()  asm volatile("cp.async.wait_group 1;" ::: "memory")

static __device__ __forceinline__ void split2h(float x, float y, uint32_t& h, uint32_t& l) {
    __half2 hb = __floats2half2_rn(x, y);
    float hx = __low2float(hb), hy = __high2float(hb);
    __half2 lb = __floats2half2_rn(x - hx, y - hy);
    h = *reinterpret_cast<uint32_t*>(&hb);
    l = *reinterpret_cast<uint32_t*>(&lb);
}

__global__ void deg_kernel(const int* __restrict__ ei) {
    int i = blockIdx.x * blockDim.x + threadIdx.x;
    if (i >= NN) return;
    int c = 1;
#pragma unroll
    for (int j = 0; j < 3; j++) c += (ei[i * 3 + j] >= 0);
    g_rsd[i] = rsqrtf((float)c);
}

// fp32 -> fp16 hi only (for activations)
__global__ void tohalf_kernel(const float* __restrict__ src,
                              __half* __restrict__ hi, int n4) {
    int i = blockIdx.x * blockDim.x + threadIdx.x;
    if (i >= n4) return;
    float4 v = ((const float4*)src)[i];
    __half2 a = __floats2half2_rn(v.x, v.y);
    __half2 b = __floats2half2_rn(v.z, v.w);
    ((uint2*)hi)[i] = make_uint2(*(uint32_t*)&a, *(uint32_t*)&b);
}

// fp32 -> fp16 hi/lo (for weights)
__global__ void split_kernel(const float* __restrict__ src,
                             __half* __restrict__ hi,
                             __half* __restrict__ lo, int n4) {
    int i = blockIdx.x * blockDim.x + threadIdx.x;
    if (i >= n4) return;
    float4 v = ((const float4*)src)[i];
    uint32_t h0, l0, h1, l1;
    split2h(v.x, v.y, h0, l0);
    split2h(v.z, v.w, h1, l1);
    ((uint2*)hi)[i] = make_uint2(h0, h1);
    ((uint2*)lo)[i] = make_uint2(l0, l1);
}

// ---------------- fp16 2-term HMMA GEMM, fp16 output ----------------
// Ch[m,n] = half( (sum_k A[m,k]*(Whi[n,k]+Wlo[n,k]) + bias[n]) * rsd[m] )
static constexpr int STAGE_BYTES = 49152;
static constexpr int SMEM_TOTAL  = 1024 + 2 * STAGE_BYTES;

__global__ void __launch_bounds__(256, 2)
gemm_hmma(const __half* __restrict__ Ahi,
          const __half* __restrict__ Whi, const __half* __restrict__ Wlo,
          const float* __restrict__ bias, __half* __restrict__ Ch) {
    extern __shared__ char smem[];
    const int tid = threadIdx.x, lid = tid & 31, wid = tid >> 5;
    const int m0 = blockIdx.y * 128, n0 = blockIdx.x * 128;

    float* biasS = (float*)smem;
    if (tid < 128) biasS[tid] = bias[n0 + tid];
    const uint32_t sb = smem_u32(smem) + 1024;

    const int r = tid >> 1, h = tid & 1;
    const bool aval = (m0 + r) < NN;
    const int pa = aval ? 16 : 0;
    const __half* aSrc = Ahi + (size_t)(m0 + (aval ? r : 0)) * D;
    const __half* bHs  = Whi + (size_t)(n0 + r) * D;
    const __half* bLs  = Wlo + (size_t)(n0 + r) * D;

    float acc[2][8][4];
#pragma unroll
    for (int mt = 0; mt < 2; mt++)
#pragma unroll
        for (int nt = 0; nt < 8; nt++)
#pragma unroll
            for (int j = 0; j < 4; j++) acc[mt][nt][j] = 0.f;

    auto issue = [&](int c) {
        const int st = c & 1;
        const uint32_t dA = sb + st * STAGE_BYTES + r * 128;
        const int ko = c * 64;
#pragma unroll
        for (int j = 0; j < 4; j++) {
            const int s = 4 * h + j;
            const uint32_t so = (uint32_t)((s ^ (r & 7)) << 4);
            CP16(dA + so,         aSrc + ko + s * 8, pa);
            CP16(dA + 16384 + so, bHs  + ko + s * 8, 16);
            CP16(dA + 32768 + so, bLs  + ko + s * 8, 16);
        }
    };

    const int mbase = (wid & 3) * 32, nbase = (wid >> 2) * 64;
    const int q = lid >> 3, rr = lid & 7;

    auto compute = [&](int st) {
        const uint32_t aT = sb + st * STAGE_BYTES;
#pragma unroll
        for (int ks = 0; ks < 4; ks++) {
            uint32_t ah[2][4];
#pragma unroll
            for (int mt = 0; mt < 2; mt++) {
                int row = mbase + mt * 16 + (q & 1) * 8 + rr;
                int ch  = 2 * ks + (q >> 1);
                LDSM4(ah[mt], aT + row * 128 + ((ch ^ (row & 7)) << 4));
            }
#pragma unroll
            for (int p = 0; p < 4; p++) {
                uint32_t bh[4], bl[4];
                int nrow = nbase + p * 16 + (q >> 1) * 8 + rr;
                int ch   = 2 * ks + (q & 1);
                uint32_t off = (uint32_t)(nrow * 128 + ((ch ^ (nrow & 7)) << 4));
                LDSM4(bh, aT + 16384 + off);
                LDSM4(bl, aT + 32768 + off);
#pragma unroll
                for (int mt = 0; mt < 2; mt++)
#pragma unroll
                    for (int j = 0; j < 2; j++) {
                        float* d = acc[mt][2 * p + j];
                        MMA16816(d, ah[mt], bh[2 * j], bh[2 * j + 1]);
                        MMA16816(d, ah[mt], bl[2 * j], bl[2 * j + 1]);
                    }
            }
        }
    };

    issue(0); CP_COMMIT();
    issue(1); CP_COMMIT();

#pragma unroll 1
    for (int c = 0; c < 8; c++) {
        CP_WAIT1();
        __syncthreads();
        compute(c & 1);
        __syncthreads();
        if (c + 2 < 8) issue(c + 2);
        CP_COMMIT();
    }

    // epilogue: half((acc + bias) * rsd)
#pragma unroll
    for (int mt = 0; mt < 2; mt++)
#pragma unroll
        for (int half = 0; half < 2; half++) {
            int row = m0 + mbase + mt * 16 + (lid >> 2) + half * 8;
            if (row < NN) {
                float rs = g_rsd[row];
#pragma unroll
                for (int nt = 0; nt < 8; nt++) {
                    int colrel = nbase + nt * 8 + (lid & 3) * 2;
                    __half2 hv = __floats2half2_rn(
                        (acc[mt][nt][half * 2 + 0] + biasS[colrel + 0]) * rs,
                        (acc[mt][nt][half * 2 + 1] + biasS[colrel + 1]) * rs);
                    *(uint32_t*)(Ch + (size_t)row * D + n0 + colrel) = *(uint32_t*)&hv;
                }
            }
        }
}

// helpers: uint2 (4 halves) <-> fp32 quad accumulate
static __device__ __forceinline__ void addh4(float& a0, float& a1, float& a2, float& a3, uint2 v) {
    __half2 p = *reinterpret_cast<__half2*>(&v.x);
    __half2 q = *reinterpret_cast<__half2*>(&v.y);
    a0 += __low2float(p); a1 += __high2float(p);
    a2 += __low2float(q); a3 += __high2float(q);
}

// ---------- aggregation + ELU on fp16 h, fp16 out (feeds next GEMM) ----------
__global__ void agg_half_kernel(const __half* __restrict__ h,
                                const int* __restrict__ ei,
                                __half* __restrict__ hi) {
    const size_t node = blockIdx.x;
    const int t = threadIdx.x;  // 0..127, 4 halves each
    const uint2* hv = (const uint2*)h;

    float a0 = 0.f, a1 = 0.f, a2 = 0.f, a3 = 0.f;
    addh4(a0, a1, a2, a3, hv[node * 128 + t]);
    int e0 = ei[node * 3 + 0];
    int e1 = ei[node * 3 + 1];
    int e2 = ei[node * 3 + 2];
    if (e0 >= 0) addh4(a0, a1, a2, a3, hv[(size_t)e0 * 128 + t]);
    if (e1 >= 0) addh4(a0, a1, a2, a3, hv[(size_t)e1 * 128 + t]);
    if (e2 >= 0) addh4(a0, a1, a2, a3, hv[(size_t)e2 * 128 + t]);

    const float rs = g_rsd[node];
    a0 *= rs; a1 *= rs; a2 *= rs; a3 *= rs;
    a0 = a0 > 0.f ? a0 : expm1f(a0);
    a1 = a1 > 0.f ? a1 : expm1f(a1);
    a2 = a2 > 0.f ? a2 : expm1f(a2);
    a3 = a3 > 0.f ? a3 : expm1f(a3);

    __half2 p = __floats2half2_rn(a0, a1);
    __half2 q = __floats2half2_rn(a2, a3);
    ((uint2*)hi)[node * 128 + t] = make_uint2(*(uint32_t*)&p, *(uint32_t*)&q);
}

// ---------- final aggregation + ELU, fp32 out ----------
__global__ void agg_final_kernel(const __half* __restrict__ h,
                                 const int* __restrict__ ei,
                                 float* __restrict__ out) {
    const size_t node = blockIdx.x;
    const int t = threadIdx.x;
    const uint2* hv = (const uint2*)h;

    float a0 = 0.f, a1 = 0.f, a2 = 0.f, a3 = 0.f;
    addh4(a0, a1, a2, a3, hv[node * 128 + t]);
    int e0 = ei[node * 3 + 0];
    int e1 = ei[node * 3 + 1];
    int e2 = ei[node * 3 + 2];
    if (e0 >= 0) addh4(a0, a1, a2, a3, hv[(size_t)e0 * 128 + t]);
    if (e1 >= 0) addh4(a0, a1, a2, a3, hv[(size_t)e1 * 128 + t]);
    if (e2 >= 0) addh4(a0, a1, a2, a3, hv[(size_t)e2 * 128 + t]);

    const float rs = g_rsd[node];
    a0 *= rs; a1 *= rs; a2 *= rs; a3 *= rs;
    float4 o;
    o.x = a0 > 0.f ? a0 : expm1f(a0);
    o.y = a1 > 0.f ? a1 : expm1f(a1);
    o.z = a2 > 0.f ? a2 : expm1f(a2);
    o.w = a3 > 0.f ? a3 : expm1f(a3);
    ((float4*)out)[node * 128 + t] = o;
}

extern "C" void kernel_launch(void* const* d_in, const int* in_sizes, int n_in,
                              void* d_out, int out_size) {
    const float* x  = nullptr;
    const int*   ei = nullptr;
    const float* Wt[2] = {nullptr, nullptr};
    const float* bt[2] = {nullptr, nullptr};
    int wi = 0, bi = 0;
    for (int i = 0; i < n_in; i++) {
        int sz = in_sizes[i];
        if (sz == NN * D)      x = (const float*)d_in[i];
        else if (sz == NN * 3) ei = (const int*)d_in[i];
        else if (sz == D * D)  { if (wi < 2) Wt[wi++] = (const float*)d_in[i]; }
        else if (sz == D)      { if (bi < 2) bt[bi++] = (const float*)d_in[i]; }
    }
    float* out = (float*)d_out;

    void *ph, *pah, *pw1h, *pw1l, *pw2h, *pw2l;
    cudaGetSymbolAddress(&ph,  g_h);
    cudaGetSymbolAddress(&pah, g_ahi);
    cudaGetSymbolAddress(&pw1h, g_w1hi);
    cudaGetSymbolAddress(&pw1l, g_w1lo);
    cudaGetSymbolAddress(&pw2h, g_w2hi);
    cudaGetSymbolAddress(&pw2l, g_w2lo);
    __half* hbuf = (__half*)ph;
    __half* ahi = (__half*)pah;
    __half *w1hi = (__half*)pw1h, *w1lo = (__half*)pw1l;
    __half *w2hi = (__half*)pw2h, *w2lo = (__half*)pw2l;

    cudaFuncSetAttribute(gemm_hmma, cudaFuncAttributeMaxDynamicSharedMemorySize, SMEM_TOTAL);

    deg_kernel<<<(NN + 255) / 256, 256>>>(ei);
    tohalf_kernel<<<(NN * D / 4 + 255) / 256, 256>>>(x, ahi, NN * D / 4);
    split_kernel<<<(D * D / 4 + 255) / 256, 256>>>(Wt[0], w1hi, w1lo, D * D / 4);
    split_kernel<<<(D * D / 4 + 255) / 256, 256>>>(Wt[1], w2hi, w2lo, D * D / 4);

    dim3 ggrid(D / 128, (NN + 127) / 128);  // (4, 782)
    gemm_hmma<<<ggrid, 256, SMEM_TOTAL>>>(ahi, w1hi, w1lo, bt[0], hbuf);
    agg_half_kernel<<<NN, 128>>>(hbuf, ei, ahi);
    gemm_hmma<<<ggrid, 256, SMEM_TOTAL>>>(ahi, w2hi, w2lo, bt[1], hbuf);
    agg_final_kernel<<<NN, 128>>>(hbuf, ei, out);
}